// round 12
// baseline (speedup 1.0000x reference)
#include <cuda_runtime.h>
#include <cuda_bf16.h>
#include <math.h>
#include <stdint.h>

#define N_NODES 10000
#define N_EDGES 320000
#define IN_DIM  10000
#define HID     128
#define NCLS    2

// ---------------- scratch (no allocs allowed) --------------------------------
__device__ float g_h[(size_t)N_NODES * HID];     // x @ W_conv (atomic-accumulated)
__device__ float g_agg[(size_t)N_NODES * HID];   // aggregated messages (edges only)
__device__ float g_deg[N_NODES];                 // 1 + sum of incoming edge weights
__device__ int   g_is32;                         // edge_index dtype flag
__device__ __nv_bfloat16 g_Wt_hi[(size_t)HID * IN_DIM];  // W^T hi split [128][10000]
__device__ __nv_bfloat16 g_Wt_lo[(size_t)HID * IN_DIM];  // W^T lo split

// ---------------- helpers ----------------------------------------------------
__device__ __forceinline__ uint32_t smem_u32(const void* p) {
    uint32_t a;
    asm("{ .reg .u64 t; cvta.to.shared.u64 t, %1; cvt.u32.u64 %0, t; }"
        : "=r"(a) : "l"(p));
    return a;
}

#define LDSM4(r, addr)                                                         \
    asm volatile("ldmatrix.sync.aligned.m8n8.x4.shared.b16 {%0,%1,%2,%3}, [%4];" \
                 : "=r"((r)[0]), "=r"((r)[1]), "=r"((r)[2]), "=r"((r)[3])      \
                 : "r"(addr))

#define MMA16816(d, a, b0, b1)                                                 \
    asm volatile("mma.sync.aligned.m16n8k16.row.col.f32.bf16.bf16.f32 "        \
                 "{%0,%1,%2,%3}, {%4,%5,%6,%7}, {%8,%9}, {%0,%1,%2,%3};"       \
                 : "+f"((d)[0]), "+f"((d)[1]), "+f"((d)[2]), "+f"((d)[3])      \
                 : "r"((a)[0]), "r"((a)[1]), "r"((a)[2]), "r"((a)[3]),         \
                   "r"(b0), "r"(b1))

// ---------------- prep: wsplit + zero g_h/g_agg + deg=1 + dtype detect -------
#define WSPLIT_BLOCKS 1252
__global__ __launch_bounds__(256) void k_prep(const float* __restrict__ W,
                                              const long long* ei) {
    __shared__ float t[32][33];
    int bid = blockIdx.x;
    if (bid < WSPLIT_BLOCKS) {
        int kb = (bid % 313) * 32, nb = (bid / 313) * 32;
        int tx = threadIdx.x & 31, ty = threadIdx.x >> 5;   // ty 0..7
#pragma unroll
        for (int r = ty; r < 32; r += 8) {
            int k = kb + r;
            t[r][tx] = (k < IN_DIM) ? W[(size_t)k * HID + nb + tx] : 0.0f;
        }
        __syncthreads();
#pragma unroll
        for (int r = ty; r < 32; r += 8) {
            int n = nb + r;
            int k = kb + tx;
            if (k < IN_DIM) {
                float v = t[tx][r];
                __nv_bfloat16 hi = __float2bfloat16(v);
                __nv_bfloat16 lo = __float2bfloat16(v - __bfloat162float(hi));
                g_Wt_hi[(size_t)n * IN_DIM + k] = hi;
                g_Wt_lo[(size_t)n * IN_DIM + k] = lo;
            }
        }
    } else {
        int i = (bid - WSPLIT_BLOCKS) * 256 + threadIdx.x;
        if (i < (N_NODES * HID) / 4) {
            ((float4*)g_h)[i]   = make_float4(0.f, 0.f, 0.f, 0.f);
            ((float4*)g_agg)[i] = make_float4(0.f, 0.f, 0.f, 0.f);
        }
        if (i < N_NODES) g_deg[i] = 1.0f;   // self-loop weight
        if (i == 0) {
            int is32 = 0;
            for (int j = 0; j < 16; j++) {
                long long v = ei[j];
                if (v < 0 || v >= N_NODES) { is32 = 1; break; }
            }
            g_is32 = is32;
        }
    }
}
__device__ __forceinline__ int edge_idx(const void* ei, long long i) {
    if (g_is32) return ((const int*)ei)[i];
    return (int)((const long long*)ei)[i];
}

__global__ void k_deg_accum(const void* ei, const float* __restrict__ ew) {
    int e = blockIdx.x * blockDim.x + threadIdx.x;
    if (e < N_EDGES) {
        int c = edge_idx(ei, (long long)N_EDGES + e);
        atomicAdd(&g_deg[c], ew[e]);
    }
}

// ---------------- HMMA GEMM: h = x @ W_conv (bf16x3 split, K-split x4) -------
// BM=64, BN=128, BK=64; 256 threads = 8 warps in 2x4; warptile 32x32.
// smem 110.6 KB + <=128 regs/thread -> 2 CTAs/SM: cross-CTA warps cover the
// end-of-chunk barrier-stall windows that a single 512-thread CTA pays raw.
#define BM 64
#define BN 128
#define BK 64
#define STR 72                          // padded smem row stride (144 B)
#define NCHT ((IN_DIM + BK - 1) / BK)   // 157 total chunks
#define KSPL 4
#define CPS  ((NCHT + KSPL - 1) / KSPL) // 40 chunks per split (last: 37)
#define ABLK (BM * STR * 2)             // 9216 B per (buf,dt) A block
#define BBLK (BN * STR * 2)             // 18432 B per (buf,dt) B block
#define GSMEM (4 * ABLK + 4 * BBLK)     // 110592 B

__global__ __launch_bounds__(256, 2) void k_gemm_mma(const float* __restrict__ x) {
    extern __shared__ __align__(16) char smem[];
#define SAp(buf, dt) ((__nv_bfloat16*)(smem + ((buf) * 2 + (dt)) * ABLK))
#define SBp(buf, dt) ((__nv_bfloat16*)(smem + 4 * ABLK + ((buf) * 2 + (dt)) * BBLK))

    const int tid  = threadIdx.x;
    const int lane = tid & 31;
    const int wid  = tid >> 5;
    const int wm   = wid >> 2;          // 0..1
    const int wn   = wid & 3;           // 0..3
    const int m0   = blockIdx.y * BM;
    const int cs   = blockIdx.x * CPS;
    const int ce   = min(cs + CPS, NCHT);
    const int nch  = ce - cs;

    float acc[2][4][4];
#pragma unroll
    for (int a = 0; a < 2; a++)
#pragma unroll
        for (int b = 0; b < 4; b++)
#pragma unroll
            for (int c = 0; c < 4; c++) acc[a][b][c] = 0.0f;

    float4 pa[4];

// A tile: 64 rows x 16 float4; 256 threads x 4 iters.
#define LOADGA(cc)                                                             \
    {                                                                          \
        const int k0 = (cc) * BK;                                              \
        _Pragma("unroll")                                                      \
        for (int i = 0; i < 4; i++) {                                          \
            int q = tid + 256 * i, row = q >> 4, c4 = q & 15;                  \
            int gm = m0 + row, k = k0 + c4 * 4;                                \
            pa[i] = (gm < N_NODES && k < IN_DIM)                               \
                        ? *(const float4*)(x + (size_t)gm * IN_DIM + k)        \
                        : make_float4(0.f, 0.f, 0.f, 0.f);                     \
        }                                                                      \
    }

#define STORESA(p)                                                             \
    {                                                                          \
        _Pragma("unroll")                                                      \
        for (int i = 0; i < 4; i++) {                                          \
            int q = tid + 256 * i, row = q >> 4, c4 = q & 15;                  \
            float4 v = pa[i];                                                  \
            __nv_bfloat162 h0 = __float22bfloat162_rn(make_float2(v.x, v.y));  \
            __nv_bfloat162 h1 = __float22bfloat162_rn(make_float2(v.z, v.w));  \
            float2 f0 = __bfloat1622float2(h0), f1 = __bfloat1622float2(h1);   \
            __nv_bfloat162 l0 = __float22bfloat162_rn(                         \
                make_float2(v.x - f0.x, v.y - f0.y));                          \
            __nv_bfloat162 l1 = __float22bfloat162_rn(                         \
                make_float2(v.z - f1.x, v.w - f1.y));                          \
            uint2 hh = make_uint2(*(uint32_t*)&h0, *(uint32_t*)&h1);           \
            uint2 ll = make_uint2(*(uint32_t*)&l0, *(uint32_t*)&l1);           \
            *(uint2*)(SAp(p, 0) + row * STR + c4 * 4) = hh;                    \
            *(uint2*)(SAp(p, 1) + row * STR + c4 * 4) = ll;                    \
        }                                                                      \
    }

// B tile: 128 rows x 8 uint4 per dt; 256 threads: row = tid>>1, 4 grps x 2 dt.
#define CPB(p, cc)                                                             \
    {                                                                          \
        int row = tid >> 1, c4 = tid & 1;                                      \
        _Pragma("unroll")                                                      \
        for (int g2 = 0; g2 < 4; g2++) {                                       \
            int grp = c4 + g2 * 2;                                             \
            int k = (cc) * BK + grp * 8;                                       \
            if (k + 8 <= IN_DIM) {                                             \
                uint32_t dh = smem_u32(SBp(p, 0) + row * STR + grp * 8);       \
                uint32_t dl = smem_u32(SBp(p, 1) + row * STR + grp * 8);       \
                const void* sh = g_Wt_hi + (size_t)row * IN_DIM + k;           \
                const void* sl = g_Wt_lo + (size_t)row * IN_DIM + k;           \
                asm volatile("cp.async.ca.shared.global [%0], [%1], 16;"       \
                             :: "r"(dh), "l"(sh));                             \
                asm volatile("cp.async.ca.shared.global [%0], [%1], 16;"       \
                             :: "r"(dl), "l"(sl));                             \
            } else {                                                           \
                uint4 z = make_uint4(0, 0, 0, 0);                              \
                *(uint4*)(SBp(p, 0) + row * STR + grp * 8) = z;                \
                *(uint4*)(SBp(p, 1) + row * STR + grp * 8) = z;                \
            }                                                                  \
        }                                                                      \
        asm volatile("cp.async.commit_group;");                                \
    }

#define FRAGS(ks)                                                              \
    {                                                                          \
        _Pragma("unroll")                                                      \
        for (int mi = 0; mi < 2; mi++) {                                       \
            uint32_t off = (uint32_t)((wm * 32 + mi * 16 + lr) * STR) * 2 +    \
                           (ks) * 32 + lc * 16;                                \
            LDSM4(ah[mi], aHi + off);                                          \
            LDSM4(al[mi], aLo + off);                                          \
        }                                                                      \
        _Pragma("unroll")                                                      \
        for (int g = 0; g < 2; g++) {                                          \
            uint32_t off = (uint32_t)((wn * 32 + g * 16 + lr) * STR) * 2 +     \
                           (ks) * 32 + lc * 16;                                \
            LDSM4(bh[g], bHi + off);                                           \
            LDSM4(bl[g], bLo + off);                                           \
        }                                                                      \
    }

#define MMAS()                                                                 \
    {                                                                          \
        _Pragma("unroll")                                                      \
        for (int mi = 0; mi < 2; mi++)                                         \
            _Pragma("unroll")                                                  \
            for (int ni = 0; ni < 4; ni++) {                                   \
                int g = ni >> 1, h = ni & 1;                                   \
                MMA16816(acc[mi][ni], ah[mi], bh[g][h], bh[g][h + 2]);         \
            }                                                                  \
        _Pragma("unroll")                                                      \
        for (int mi = 0; mi < 2; mi++)                                         \
            _Pragma("unroll")                                                  \
            for (int ni = 0; ni < 4; ni++) {                                   \
                int g = ni >> 1, h = ni & 1;                                   \
                MMA16816(acc[mi][ni], ah[mi], bl[g][h], bl[g][h + 2]);         \
            }                                                                  \
        _Pragma("unroll")                                                      \
        for (int mi = 0; mi < 2; mi++)                                         \
            _Pragma("unroll")                                                  \
            for (int ni = 0; ni < 4; ni++) {                                   \
                int g = ni >> 1, h = ni & 1;                                   \
                MMA16816(acc[mi][ni], al[mi], bh[g][h], bh[g][h + 2]);         \
            }                                                                  \
    }

    // prologue: fill buf 0 with chunk cs; prefetch chunk cs+1 into registers
    LOADGA(cs);
    STORESA(0);
    CPB(0, cs);
    LOADGA(cs + 1);
    asm volatile("cp.async.wait_group 0;" ::: "memory");
    __syncthreads();

    const int lr = lane & 15;
    const int lc = lane >> 4;

    for (int ci = 0; ci < nch; ci++) {
        const int p = ci & 1;
        const uint32_t aHi = smem_u32(SAp(p, 0));
        const uint32_t aLo = smem_u32(SAp(p, 1));
        const uint32_t bHi = smem_u32(SBp(p, 0));
        const uint32_t bLo = smem_u32(SBp(p, 1));

        uint32_t ah[2][4], al[2][4], bh[2][4], bl[2][4];

        // first half of the chunk: tensor work starts right after the barrier
        FRAGS(0);
        MMAS();
        FRAGS(1);
        MMAS();

        // mid-chunk feed (prefetch for chunk ci+1 overlaps remaining MMAs)
        if (ci + 1 < nch) { STORESA((ci + 1) & 1); CPB((ci + 1) & 1, cs + ci + 1); }
        if (ci + 2 < nch) LOADGA(cs + ci + 2);

        // second half
        FRAGS(2);
        MMAS();
        FRAGS(3);
        MMAS();

        asm volatile("cp.async.wait_group 0;" ::: "memory");
        __syncthreads();
    }

    // epilogue: atomic-accumulate partial sums into g_h
#pragma unroll
    for (int mi = 0; mi < 2; mi++) {
#pragma unroll
        for (int half = 0; half < 2; half++) {
            int row = m0 + wm * 32 + mi * 16 + (lane >> 2) + half * 8;
            if (row < N_NODES) {
#pragma unroll
                for (int ni = 0; ni < 4; ni++) {
                    int col = wn * 32 + ni * 8 + (lane & 3) * 2;
                    float v0 = acc[mi][ni][2 * half];
                    float v1 = acc[mi][ni][2 * half + 1];
                    float* hp = g_h + (size_t)row * HID + col;
                    asm volatile("red.global.add.v2.f32 [%0], {%1, %2};"
                                 :: "l"(hp), "f"(v0), "f"(v1) : "memory");
                }
            }
        }
    }
#undef LOADGA
#undef STORESA
#undef CPB
#undef FRAGS
#undef MMAS
#undef SAp
#undef SBp
}

// ---------------- edge scatter: one warp per edge, vector RED ----------------
__global__ __launch_bounds__(256) void k_scatter(const void* ei,
                                                 const float* __restrict__ ew) {
    int gw   = blockIdx.x * 8 + (threadIdx.x >> 5);
    int lane = threadIdx.x & 31;
    if (gw >= N_EDGES) return;
    int r = edge_idx(ei, gw);                          // row (source)
    int c = edge_idx(ei, (long long)N_EDGES + gw);     // col (dest)
    float w = rsqrtf(g_deg[r]) * ew[gw] * rsqrtf(g_deg[c]);
    float4 v = ((const float4*)(g_h + (size_t)r * HID))[lane];
    float* ap = g_agg + (size_t)c * HID + lane * 4;
    asm volatile("red.global.add.v4.f32 [%0], {%1, %2, %3, %4};"
                 :: "l"(ap), "f"(w * v.x), "f"(w * v.y), "f"(w * v.z), "f"(w * v.w)
                 : "memory");
}

// ---------------- head: relu(agg + dinv^2*h + b_conv) @ W_lin, softmax -------
__global__ __launch_bounds__(256) void k_head(const float* __restrict__ b_conv,
                                              const float* __restrict__ W_lin,
                                              const float* __restrict__ b_lin,
                                              float* __restrict__ out) {
    int i    = blockIdx.x * 8 + (threadIdx.x >> 5);
    int lane = threadIdx.x & 31;
    if (i >= N_NODES) return;

    float dr = rsqrtf(g_deg[i]);
    float d2 = dr * dr;
    float4 v  = ((const float4*)(g_agg + (size_t)i * HID))[lane];
    float4 hv = ((const float4*)(g_h   + (size_t)i * HID))[lane];
    float4 b  = ((const float4*)b_conv)[lane];
    v.x = fmaxf(v.x + d2 * hv.x + b.x, 0.0f);
    v.y = fmaxf(v.y + d2 * hv.y + b.y, 0.0f);
    v.z = fmaxf(v.z + d2 * hv.z + b.z, 0.0f);
    v.w = fmaxf(v.w + d2 * hv.w + b.w, 0.0f);

    int k = lane * 4;
    float l0 = v.x * W_lin[(k + 0) * 2 + 0] + v.y * W_lin[(k + 1) * 2 + 0] +
               v.z * W_lin[(k + 2) * 2 + 0] + v.w * W_lin[(k + 3) * 2 + 0];
    float l1 = v.x * W_lin[(k + 0) * 2 + 1] + v.y * W_lin[(k + 1) * 2 + 1] +
               v.z * W_lin[(k + 2) * 2 + 1] + v.w * W_lin[(k + 3) * 2 + 1];

#pragma unroll
    for (int off = 16; off > 0; off >>= 1) {
        l0 += __shfl_xor_sync(0xFFFFFFFFu, l0, off);
        l1 += __shfl_xor_sync(0xFFFFFFFFu, l1, off);
    }

    if (lane == 0) {
        l0 += b_lin[0];
        l1 += b_lin[1];
        float m  = fmaxf(l0, l1);
        float e0 = expf(l0 - m), e1 = expf(l1 - m);
        float s  = e0 + e1;
        out[i * 2 + 0] = e0 / s;
        out[i * 2 + 1] = e1 / s;
    }
}

// -----------------------------------------------------------------------------
extern "C" void kernel_launch(void* const* d_in, const int* in_sizes, int n_in,
                              void* d_out, int out_size) {
    const float* x      = (const float*)d_in[0];
    const void*  ei     = d_in[1];                  // int64 or int32 (detected)
    const float* ew     = (const float*)d_in[2];
    const float* W_conv = (const float*)d_in[3];
    const float* b_conv = (const float*)d_in[4];
    const float* W_lin  = (const float*)d_in[5];
    const float* b_lin  = (const float*)d_in[6];
    float* out = (float*)d_out;

    cudaFuncSetAttribute(k_gemm_mma, cudaFuncAttributeMaxDynamicSharedMemorySize,
                         GSMEM);

    k_prep<<<WSPLIT_BLOCKS + 1250, 256>>>(W_conv, (const long long*)ei);
    k_deg_accum<<<(N_EDGES + 255) / 256, 256>>>(ei, ew);
    dim3 gg(KSPL, (N_NODES + BM - 1) / BM);       // (4, 157) = 628 CTAs
    k_gemm_mma<<<gg, 256, GSMEM>>>(x);
    k_scatter<<<(N_EDGES + 7) / 8, 256>>>(ei, ew);
    k_head<<<(N_NODES + 7) / 8, 256>>>(b_conv, W_lin, b_lin, out);
}